// round 5
// baseline (speedup 1.0000x reference)
#include <cuda_runtime.h>

// Problem constants (fixed-shape problem)
#define BATCH   4
#define SEQ     2048
#define DMODEL  1024
#define NHEADS  16
#define DHEAD   64
#define SCALE   0.125f          // 1/sqrt(64)
#define MROWS   (BATCH * SEQ)   // 8192

// Scratch (device globals: allocation-free per harness rules)
__device__ float g_Q [BATCH * NHEADS * SEQ * DHEAD];
__device__ float g_K [BATCH * NHEADS * SEQ * DHEAD];
__device__ float g_V [BATCH * NHEADS * SEQ * DHEAD];
__device__ float g_AO[MROWS * DMODEL];

// ---------------------------------------------------------------------------
// QKV projection: Out[n,m] = sum_k X[m,k] * W[n,k]  (x @ W^T), written into
// [B,H,T,DH] head-major layout. blockIdx.z selects Q/K/V.
// 64x64 block tile, 256 threads, 4x4 micro-tile, K-tile 16.
// ---------------------------------------------------------------------------
__global__ __launch_bounds__(256) void qkv_kernel(
    const float* __restrict__ X,
    const float* __restrict__ Wq,
    const float* __restrict__ Wk,
    const float* __restrict__ Wv)
{
    __shared__ float As[16][68];   // [k][m], +4 pad: 16B-aligned rows, low STS conflict
    __shared__ float Bs[16][68];   // [k][n]

    const float* W   = (blockIdx.z == 0) ? Wq : (blockIdx.z == 1 ? Wk : Wv);
    float*       Out = (blockIdx.z == 0) ? g_Q : (blockIdx.z == 1 ? g_K : g_V);

    const int tid  = threadIdx.x;
    const int row  = tid >> 4;          // 0..15
    const int col  = tid & 15;          // 0..15
    const int m0   = blockIdx.y * 64;
    const int n0   = blockIdx.x * 64;
    const int lm   = tid >> 2;          // 0..63 (loader row)
    const int lk   = (tid & 3) << 2;    // 0,4,8,12 (loader k)

    float acc[4][4] = {};

#pragma unroll 1
    for (int k0 = 0; k0 < DMODEL; k0 += 16) {
        float4 a = *(const float4*)(X + (size_t)(m0 + lm) * DMODEL + k0 + lk);
        float4 b = *(const float4*)(W + (size_t)(n0 + lm) * DMODEL + k0 + lk);
        __syncthreads();   // previous tile's compute done before overwrite
        As[lk + 0][lm] = a.x; As[lk + 1][lm] = a.y; As[lk + 2][lm] = a.z; As[lk + 3][lm] = a.w;
        Bs[lk + 0][lm] = b.x; Bs[lk + 1][lm] = b.y; Bs[lk + 2][lm] = b.z; Bs[lk + 3][lm] = b.w;
        __syncthreads();
#pragma unroll
        for (int k = 0; k < 16; k++) {
            float4 av = *(const float4*)&As[k][row * 4];
            float4 bv = *(const float4*)&Bs[k][col * 4];
            float aa[4] = {av.x, av.y, av.z, av.w};
            float bb[4] = {bv.x, bv.y, bv.z, bv.w};
#pragma unroll
            for (int i = 0; i < 4; i++)
#pragma unroll
                for (int j = 0; j < 4; j++)
                    acc[i][j] += aa[i] * bb[j];
        }
    }

    // Write to [B,H,T,DH]: m = b*T + t, n = h*64 + dh
    const int nc = n0 + col * 4;
    const int h  = nc >> 6;
    const int dh = nc & 63;
#pragma unroll
    for (int i = 0; i < 4; i++) {
        const int m  = m0 + row * 4 + i;
        const int bb = m >> 11;            // /SEQ
        const int t  = m & 2047;
        float4 o = make_float4(acc[i][0], acc[i][1], acc[i][2], acc[i][3]);
        *(float4*)(Out + ((size_t)(bb * NHEADS + h) * SEQ + t) * DHEAD + dh) = o;
    }
}

// ---------------------------------------------------------------------------
// Flash attention (fp32, online softmax). One CTA = 64 query rows of one
// (b,h). 256 threads: thread (row,col) owns q-rows row*4..+3 and score/output
// cols col*4..+3. SMEM: Q^T, {K^T then P} (shared buffer), V = 48 KB.
// ---------------------------------------------------------------------------
__global__ __launch_bounds__(256) void attn_kernel()
{
    __shared__ float Qts[64 * 64];   // [d][q], Q pre-scaled by SCALE
    __shared__ float KP [64 * 64];   // K^T [d][k] during S; P [q][k] during PV
    __shared__ float Vs [64 * 64];   // [k][d]

    const int tid  = threadIdx.x;
    const int row  = tid >> 4;
    const int col  = tid & 15;
    const int row4 = row * 4;
    const int col4 = col * 4;

    const int bh = blockIdx.z * NHEADS + blockIdx.y;
    const float* Qg = g_Q + (size_t)bh * SEQ * DHEAD;
    const float* Kg = g_K + (size_t)bh * SEQ * DHEAD;
    const float* Vg = g_V + (size_t)bh * SEQ * DHEAD;
    const int q0 = blockIdx.x * 64;

    const int lr = tid >> 4;         // loader row 0..15
    const int lc = (tid & 15) * 4;   // loader col 0,4,..,60

    // Load Q tile transposed, scale folded in
#pragma unroll
    for (int rr = 0; rr < 4; rr++) {
        const int r = lr + rr * 16;
        float4 q = *(const float4*)(Qg + (size_t)(q0 + r) * DHEAD + lc);
        Qts[(lc + 0) * 64 + r] = q.x * SCALE;
        Qts[(lc + 1) * 64 + r] = q.y * SCALE;
        Qts[(lc + 2) * 64 + r] = q.z * SCALE;
        Qts[(lc + 3) * 64 + r] = q.w * SCALE;
    }

    float m_i[4], l_i[4], acc[4][4];
#pragma unroll
    for (int i = 0; i < 4; i++) {
        m_i[i] = -1e30f;
        l_i[i] = 0.0f;
#pragma unroll
        for (int j = 0; j < 4; j++) acc[i][j] = 0.0f;
    }

#pragma unroll 1
    for (int kt = 0; kt < SEQ / 64; kt++) {
        const int k0 = kt * 64;

        // Stage K/V tile through registers
        float4 kr[4], vr[4];
#pragma unroll
        for (int rr = 0; rr < 4; rr++) {
            const int r = lr + rr * 16;
            kr[rr] = *(const float4*)(Kg + (size_t)(k0 + r) * DHEAD + lc);
            vr[rr] = *(const float4*)(Vg + (size_t)(k0 + r) * DHEAD + lc);
        }
        __syncthreads();   // previous tile's PV reads of KP/Vs complete
#pragma unroll
        for (int rr = 0; rr < 4; rr++) {
            const int r = lr + rr * 16;
            KP[(lc + 0) * 64 + r] = kr[rr].x;
            KP[(lc + 1) * 64 + r] = kr[rr].y;
            KP[(lc + 2) * 64 + r] = kr[rr].z;
            KP[(lc + 3) * 64 + r] = kr[rr].w;
            *(float4*)&Vs[r * 64 + lc] = vr[rr];
        }
        __syncthreads();

        // S = (Q*scale) @ K^T, 4x4 per thread
        float s[4][4] = {};
#pragma unroll 8
        for (int kk = 0; kk < 64; kk++) {
            float4 qv = *(const float4*)&Qts[kk * 64 + row4];
            float4 kv = *(const float4*)&KP [kk * 64 + col4];
            float qa[4] = {qv.x, qv.y, qv.z, qv.w};
            float ka[4] = {kv.x, kv.y, kv.z, kv.w};
#pragma unroll
            for (int i = 0; i < 4; i++)
#pragma unroll
                for (int j = 0; j < 4; j++)
                    s[i][j] += qa[i] * ka[j];
        }

        // Online softmax update (per q-row, reduced over the 16 col-threads)
        float p[4][4];
#pragma unroll
        for (int i = 0; i < 4; i++) {
            float tm = fmaxf(fmaxf(s[i][0], s[i][1]), fmaxf(s[i][2], s[i][3]));
#pragma unroll
            for (int off = 8; off > 0; off >>= 1)
                tm = fmaxf(tm, __shfl_xor_sync(0xffffffffu, tm, off));
            const float mn = fmaxf(m_i[i], tm);
            const float al = __expf(m_i[i] - mn);
            m_i[i] = mn;
            float rs = 0.0f;
#pragma unroll
            for (int j = 0; j < 4; j++) {
                p[i][j] = __expf(s[i][j] - mn);
                rs += p[i][j];
            }
#pragma unroll
            for (int off = 8; off > 0; off >>= 1)
                rs += __shfl_xor_sync(0xffffffffu, rs, off);
            l_i[i] = l_i[i] * al + rs;
#pragma unroll
            for (int j = 0; j < 4; j++) acc[i][j] *= al;
        }

        __syncthreads();   // all S reads of KP done before overwriting with P
#pragma unroll
        for (int i = 0; i < 4; i++)
#pragma unroll
            for (int j = 0; j < 4; j++)
                KP[(row4 + i) * 64 + col4 + j] = p[i][j];
        __syncthreads();

        // acc += P @ V  (P read as float4 along k; V natural layout)
#pragma unroll 4
        for (int kq = 0; kq < 64; kq += 4) {
            float4 P0 = *(const float4*)&KP[(row4 + 0) * 64 + kq];
            float4 P1 = *(const float4*)&KP[(row4 + 1) * 64 + kq];
            float4 P2 = *(const float4*)&KP[(row4 + 2) * 64 + kq];
            float4 P3 = *(const float4*)&KP[(row4 + 3) * 64 + kq];
            float pa[4][4] = {{P0.x, P0.y, P0.z, P0.w},
                              {P1.x, P1.y, P1.z, P1.w},
                              {P2.x, P2.y, P2.z, P2.w},
                              {P3.x, P3.y, P3.z, P3.w}};
#pragma unroll
            for (int q = 0; q < 4; q++) {
                float4 v4 = *(const float4*)&Vs[(kq + q) * 64 + col4];
                float va[4] = {v4.x, v4.y, v4.z, v4.w};
#pragma unroll
                for (int i = 0; i < 4; i++)
#pragma unroll
                    for (int j = 0; j < 4; j++)
                        acc[i][j] += pa[i][q] * va[j];
            }
        }
    }

    // Normalize and write back to [B,T,D] interleaved layout
#pragma unroll
    for (int i = 0; i < 4; i++) {
        const float inv = 1.0f / l_i[i];
        const int t = q0 + row4 + i;
        float4 o = make_float4(acc[i][0] * inv, acc[i][1] * inv,
                               acc[i][2] * inv, acc[i][3] * inv);
        *(float4*)(g_AO + ((size_t)blockIdx.z * SEQ + t) * DMODEL
                        + blockIdx.y * DHEAD + col4) = o;
    }
}

// ---------------------------------------------------------------------------
// Output projection: out = attn @ Wo^T + bo
// ---------------------------------------------------------------------------
__global__ __launch_bounds__(256) void proj_kernel(
    const float* __restrict__ Wo,
    const float* __restrict__ bo,
    float* __restrict__ out)
{
    __shared__ float As[16][68];
    __shared__ float Bs[16][68];

    const int tid = threadIdx.x;
    const int row = tid >> 4, col = tid & 15;
    const int m0 = blockIdx.y * 64, n0 = blockIdx.x * 64;
    const int lm = tid >> 2;
    const int lk = (tid & 3) << 2;

    float acc[4][4] = {};

#pragma unroll 1
    for (int k0 = 0; k0 < DMODEL; k0 += 16) {
        float4 a = *(const float4*)(g_AO + (size_t)(m0 + lm) * DMODEL + k0 + lk);
        float4 b = *(const float4*)(Wo   + (size_t)(n0 + lm) * DMODEL + k0 + lk);
        __syncthreads();
        As[lk + 0][lm] = a.x; As[lk + 1][lm] = a.y; As[lk + 2][lm] = a.z; As[lk + 3][lm] = a.w;
        Bs[lk + 0][lm] = b.x; Bs[lk + 1][lm] = b.y; Bs[lk + 2][lm] = b.z; Bs[lk + 3][lm] = b.w;
        __syncthreads();
#pragma unroll
        for (int k = 0; k < 16; k++) {
            float4 av = *(const float4*)&As[k][row * 4];
            float4 bv = *(const float4*)&Bs[k][col * 4];
            float aa[4] = {av.x, av.y, av.z, av.w};
            float bb[4] = {bv.x, bv.y, bv.z, bv.w};
#pragma unroll
            for (int i = 0; i < 4; i++)
#pragma unroll
                for (int j = 0; j < 4; j++)
                    acc[i][j] += aa[i] * bb[j];
        }
    }

    const int nc = n0 + col * 4;
    const float4 bias = *(const float4*)(bo + nc);
#pragma unroll
    for (int i = 0; i < 4; i++) {
        const int m = m0 + row * 4 + i;
        float4 o = make_float4(acc[i][0] + bias.x, acc[i][1] + bias.y,
                               acc[i][2] + bias.z, acc[i][3] + bias.w);
        *(float4*)(out + (size_t)m * DMODEL + nc) = o;
    }
}

// ---------------------------------------------------------------------------
extern "C" void kernel_launch(void* const* d_in, const int* in_sizes, int n_in,
                              void* d_out, int out_size)
{
    const float* x  = (const float*)d_in[0];
    const float* Wq = (const float*)d_in[1];
    const float* Wk = (const float*)d_in[2];
    const float* Wv = (const float*)d_in[3];
    const float* Wo = (const float*)d_in[4];
    const float* bo = (const float*)d_in[5];
    float* out = (float*)d_out;

    dim3 blk(256);
    // QKV: grid (N/64=16, M/64=128, 3)
    qkv_kernel<<<dim3(16, 128, 3), blk>>>(x, Wq, Wk, Wv);
    // Attention: grid (T/64=32, H=16, B=4)
    attn_kernel<<<dim3(32, 16, 4), blk>>>();
    // Output projection: grid (16, 128)
    proj_kernel<<<dim3(16, 128), blk>>>(Wo, bo, out);
}

// round 10
// speedup vs baseline: 1.0002x; 1.0002x over previous
#include <cuda_runtime.h>

// Problem constants (fixed-shape problem)
#define BATCH   4
#define SEQ     2048
#define DMODEL  1024
#define NHEADS  16
#define DHEAD   64
#define SCALE   0.125f          // 1/sqrt(64)
#define MROWS   (BATCH * SEQ)   // 8192

// Scratch (device globals: allocation-free per harness rules)
__device__ float g_Q [BATCH * NHEADS * SEQ * DHEAD];
__device__ float g_K [BATCH * NHEADS * SEQ * DHEAD];
__device__ float g_V [BATCH * NHEADS * SEQ * DHEAD];
__device__ float g_AO[MROWS * DMODEL];

// ---------------------------------------------------------------------------
// QKV projection: Out[n,m] = sum_k X[m,k] * W[n,k]  (x @ W^T), written into
// [B,H,T,DH] head-major layout. blockIdx.z selects Q/K/V.
// 64x64 block tile, 256 threads, 4x4 micro-tile, K-tile 16.
// ---------------------------------------------------------------------------
__global__ __launch_bounds__(256) void qkv_kernel(
    const float* __restrict__ X,
    const float* __restrict__ Wq,
    const float* __restrict__ Wk,
    const float* __restrict__ Wv)
{
    __shared__ float As[16][68];   // [k][m], +4 pad: 16B-aligned rows, low STS conflict
    __shared__ float Bs[16][68];   // [k][n]

    const float* W   = (blockIdx.z == 0) ? Wq : (blockIdx.z == 1 ? Wk : Wv);
    float*       Out = (blockIdx.z == 0) ? g_Q : (blockIdx.z == 1 ? g_K : g_V);

    const int tid  = threadIdx.x;
    const int row  = tid >> 4;          // 0..15
    const int col  = tid & 15;          // 0..15
    const int m0   = blockIdx.y * 64;
    const int n0   = blockIdx.x * 64;
    const int lm   = tid >> 2;          // 0..63 (loader row)
    const int lk   = (tid & 3) << 2;    // 0,4,8,12 (loader k)

    float acc[4][4] = {};

#pragma unroll 1
    for (int k0 = 0; k0 < DMODEL; k0 += 16) {
        float4 a = *(const float4*)(X + (size_t)(m0 + lm) * DMODEL + k0 + lk);
        float4 b = *(const float4*)(W + (size_t)(n0 + lm) * DMODEL + k0 + lk);
        __syncthreads();   // previous tile's compute done before overwrite
        As[lk + 0][lm] = a.x; As[lk + 1][lm] = a.y; As[lk + 2][lm] = a.z; As[lk + 3][lm] = a.w;
        Bs[lk + 0][lm] = b.x; Bs[lk + 1][lm] = b.y; Bs[lk + 2][lm] = b.z; Bs[lk + 3][lm] = b.w;
        __syncthreads();
#pragma unroll
        for (int k = 0; k < 16; k++) {
            float4 av = *(const float4*)&As[k][row * 4];
            float4 bv = *(const float4*)&Bs[k][col * 4];
            float aa[4] = {av.x, av.y, av.z, av.w};
            float bb[4] = {bv.x, bv.y, bv.z, bv.w};
#pragma unroll
            for (int i = 0; i < 4; i++)
#pragma unroll
                for (int j = 0; j < 4; j++)
                    acc[i][j] += aa[i] * bb[j];
        }
    }

    // Write to [B,H,T,DH]: m = b*T + t, n = h*64 + dh
    const int nc = n0 + col * 4;
    const int h  = nc >> 6;
    const int dh = nc & 63;
#pragma unroll
    for (int i = 0; i < 4; i++) {
        const int m  = m0 + row * 4 + i;
        const int bb = m >> 11;            // /SEQ
        const int t  = m & 2047;
        float4 o = make_float4(acc[i][0], acc[i][1], acc[i][2], acc[i][3]);
        *(float4*)(Out + ((size_t)(bb * NHEADS + h) * SEQ + t) * DHEAD + dh) = o;
    }
}

// ---------------------------------------------------------------------------
// Flash attention (fp32, online softmax). One CTA = 64 query rows of one
// (b,h). 256 threads: thread (row,col) owns q-rows row*4..+3 and score/output
// cols col*4..+3. SMEM: Q^T, {K^T then P} (shared buffer), V = 48 KB.
// ---------------------------------------------------------------------------
__global__ __launch_bounds__(256) void attn_kernel()
{
    __shared__ float Qts[64 * 64];   // [d][q], Q pre-scaled by SCALE
    __shared__ float KP [64 * 64];   // K^T [d][k] during S; P [q][k] during PV
    __shared__ float Vs [64 * 64];   // [k][d]

    const int tid  = threadIdx.x;
    const int row  = tid >> 4;
    const int col  = tid & 15;
    const int row4 = row * 4;
    const int col4 = col * 4;

    const int bh = blockIdx.z * NHEADS + blockIdx.y;
    const float* Qg = g_Q + (size_t)bh * SEQ * DHEAD;
    const float* Kg = g_K + (size_t)bh * SEQ * DHEAD;
    const float* Vg = g_V + (size_t)bh * SEQ * DHEAD;
    const int q0 = blockIdx.x * 64;

    const int lr = tid >> 4;         // loader row 0..15
    const int lc = (tid & 15) * 4;   // loader col 0,4,..,60

    // Load Q tile transposed, scale folded in
#pragma unroll
    for (int rr = 0; rr < 4; rr++) {
        const int r = lr + rr * 16;
        float4 q = *(const float4*)(Qg + (size_t)(q0 + r) * DHEAD + lc);
        Qts[(lc + 0) * 64 + r] = q.x * SCALE;
        Qts[(lc + 1) * 64 + r] = q.y * SCALE;
        Qts[(lc + 2) * 64 + r] = q.z * SCALE;
        Qts[(lc + 3) * 64 + r] = q.w * SCALE;
    }

    float m_i[4], l_i[4], acc[4][4];
#pragma unroll
    for (int i = 0; i < 4; i++) {
        m_i[i] = -1e30f;
        l_i[i] = 0.0f;
#pragma unroll
        for (int j = 0; j < 4; j++) acc[i][j] = 0.0f;
    }

#pragma unroll 1
    for (int kt = 0; kt < SEQ / 64; kt++) {
        const int k0 = kt * 64;

        // Stage K/V tile through registers
        float4 kr[4], vr[4];
#pragma unroll
        for (int rr = 0; rr < 4; rr++) {
            const int r = lr + rr * 16;
            kr[rr] = *(const float4*)(Kg + (size_t)(k0 + r) * DHEAD + lc);
            vr[rr] = *(const float4*)(Vg + (size_t)(k0 + r) * DHEAD + lc);
        }
        __syncthreads();   // previous tile's PV reads of KP/Vs complete
#pragma unroll
        for (int rr = 0; rr < 4; rr++) {
            const int r = lr + rr * 16;
            KP[(lc + 0) * 64 + r] = kr[rr].x;
            KP[(lc + 1) * 64 + r] = kr[rr].y;
            KP[(lc + 2) * 64 + r] = kr[rr].z;
            KP[(lc + 3) * 64 + r] = kr[rr].w;
            *(float4*)&Vs[r * 64 + lc] = vr[rr];
        }
        __syncthreads();

        // S = (Q*scale) @ K^T, 4x4 per thread
        float s[4][4] = {};
#pragma unroll 8
        for (int kk = 0; kk < 64; kk++) {
            float4 qv = *(const float4*)&Qts[kk * 64 + row4];
            float4 kv = *(const float4*)&KP [kk * 64 + col4];
            float qa[4] = {qv.x, qv.y, qv.z, qv.w};
            float ka[4] = {kv.x, kv.y, kv.z, kv.w};
#pragma unroll
            for (int i = 0; i < 4; i++)
#pragma unroll
                for (int j = 0; j < 4; j++)
                    s[i][j] += qa[i] * ka[j];
        }

        // Online softmax update (per q-row, reduced over the 16 col-threads)
        float p[4][4];
#pragma unroll
        for (int i = 0; i < 4; i++) {
            float tm = fmaxf(fmaxf(s[i][0], s[i][1]), fmaxf(s[i][2], s[i][3]));
#pragma unroll
            for (int off = 8; off > 0; off >>= 1)
                tm = fmaxf(tm, __shfl_xor_sync(0xffffffffu, tm, off));
            const float mn = fmaxf(m_i[i], tm);
            const float al = __expf(m_i[i] - mn);
            m_i[i] = mn;
            float rs = 0.0f;
#pragma unroll
            for (int j = 0; j < 4; j++) {
                p[i][j] = __expf(s[i][j] - mn);
                rs += p[i][j];
            }
#pragma unroll
            for (int off = 8; off > 0; off >>= 1)
                rs += __shfl_xor_sync(0xffffffffu, rs, off);
            l_i[i] = l_i[i] * al + rs;
#pragma unroll
            for (int j = 0; j < 4; j++) acc[i][j] *= al;
        }

        __syncthreads();   // all S reads of KP done before overwriting with P
#pragma unroll
        for (int i = 0; i < 4; i++)
#pragma unroll
            for (int j = 0; j < 4; j++)
                KP[(row4 + i) * 64 + col4 + j] = p[i][j];
        __syncthreads();

        // acc += P @ V  (P read as float4 along k; V natural layout)
#pragma unroll 4
        for (int kq = 0; kq < 64; kq += 4) {
            float4 P0 = *(const float4*)&KP[(row4 + 0) * 64 + kq];
            float4 P1 = *(const float4*)&KP[(row4 + 1) * 64 + kq];
            float4 P2 = *(const float4*)&KP[(row4 + 2) * 64 + kq];
            float4 P3 = *(const float4*)&KP[(row4 + 3) * 64 + kq];
            float pa[4][4] = {{P0.x, P0.y, P0.z, P0.w},
                              {P1.x, P1.y, P1.z, P1.w},
                              {P2.x, P2.y, P2.z, P2.w},
                              {P3.x, P3.y, P3.z, P3.w}};
#pragma unroll
            for (int q = 0; q < 4; q++) {
                float4 v4 = *(const float4*)&Vs[(kq + q) * 64 + col4];
                float va[4] = {v4.x, v4.y, v4.z, v4.w};
#pragma unroll
                for (int i = 0; i < 4; i++)
#pragma unroll
                    for (int j = 0; j < 4; j++)
                        acc[i][j] += pa[i][q] * va[j];
            }
        }
    }

    // Normalize and write back to [B,T,D] interleaved layout
#pragma unroll
    for (int i = 0; i < 4; i++) {
        const float inv = 1.0f / l_i[i];
        const int t = q0 + row4 + i;
        float4 o = make_float4(acc[i][0] * inv, acc[i][1] * inv,
                               acc[i][2] * inv, acc[i][3] * inv);
        *(float4*)(g_AO + ((size_t)blockIdx.z * SEQ + t) * DMODEL
                        + blockIdx.y * DHEAD + col4) = o;
    }
}

// ---------------------------------------------------------------------------
// Output projection: out = attn @ Wo^T + bo
// ---------------------------------------------------------------------------
__global__ __launch_bounds__(256) void proj_kernel(
    const float* __restrict__ Wo,
    const float* __restrict__ bo,
    float* __restrict__ out)
{
    __shared__ float As[16][68];
    __shared__ float Bs[16][68];

    const int tid = threadIdx.x;
    const int row = tid >> 4, col = tid & 15;
    const int m0 = blockIdx.y * 64, n0 = blockIdx.x * 64;
    const int lm = tid >> 2;
    const int lk = (tid & 3) << 2;

    float acc[4][4] = {};

#pragma unroll 1
    for (int k0 = 0; k0 < DMODEL; k0 += 16) {
        float4 a = *(const float4*)(g_AO + (size_t)(m0 + lm) * DMODEL + k0 + lk);
        float4 b = *(const float4*)(Wo   + (size_t)(n0 + lm) * DMODEL + k0 + lk);
        __syncthreads();
        As[lk + 0][lm] = a.x; As[lk + 1][lm] = a.y; As[lk + 2][lm] = a.z; As[lk + 3][lm] = a.w;
        Bs[lk + 0][lm] = b.x; Bs[lk + 1][lm] = b.y; Bs[lk + 2][lm] = b.z; Bs[lk + 3][lm] = b.w;
        __syncthreads();
#pragma unroll
        for (int k = 0; k < 16; k++) {
            float4 av = *(const float4*)&As[k][row * 4];
            float4 bv = *(const float4*)&Bs[k][col * 4];
            float aa[4] = {av.x, av.y, av.z, av.w};
            float bb[4] = {bv.x, bv.y, bv.z, bv.w};
#pragma unroll
            for (int i = 0; i < 4; i++)
#pragma unroll
                for (int j = 0; j < 4; j++)
                    acc[i][j] += aa[i] * bb[j];
        }
    }

    const int nc = n0 + col * 4;
    const float4 bias = *(const float4*)(bo + nc);
#pragma unroll
    for (int i = 0; i < 4; i++) {
        const int m = m0 + row * 4 + i;
        float4 o = make_float4(acc[i][0] + bias.x, acc[i][1] + bias.y,
                               acc[i][2] + bias.z, acc[i][3] + bias.w);
        *(float4*)(out + (size_t)m * DMODEL + nc) = o;
    }
}

// ---------------------------------------------------------------------------
extern "C" void kernel_launch(void* const* d_in, const int* in_sizes, int n_in,
                              void* d_out, int out_size)
{
    const float* x  = (const float*)d_in[0];
    const float* Wq = (const float*)d_in[1];
    const float* Wk = (const float*)d_in[2];
    const float* Wv = (const float*)d_in[3];
    const float* Wo = (const float*)d_in[4];
    const float* bo = (const float*)d_in[5];
    float* out = (float*)d_out;

    dim3 blk(256);
    // QKV: grid (N/64=16, M/64=128, 3)
    qkv_kernel<<<dim3(16, 128, 3), blk>>>(x, Wq, Wk, Wv);
    // Attention: grid (T/64=32, H=16, B=4)
    attn_kernel<<<dim3(32, 16, 4), blk>>>();
    // Output projection: grid (16, 128)
    proj_kernel<<<dim3(16, 128), blk>>>(Wo, bo, out);
}